// round 6
// baseline (speedup 1.0000x reference)
#include <cuda_runtime.h>
#include <cstdint>

#define BATCH 512
#define SEQ   512
#define EMB   128
#define HID   64
#define GATES 256   // 4*HID
#define VOCAB 50000

// 51.2 MB token->xproj table: table[v][g] = dot(emb[v], Wih0[g]) + bih0[g] + bhh0[g]
__device__ float g_tab[(size_t)VOCAB * GATES];

// ---------------- packed f32x2 helpers ----------------
static __device__ __forceinline__ unsigned long long pk2(float lo, float hi) {
    unsigned long long v;
    asm("mov.b64 %0, {%1, %2};" : "=l"(v) : "f"(lo), "f"(hi));
    return v;
}
static __device__ __forceinline__ void upk2(unsigned long long v, float& lo, float& hi) {
    asm("mov.b64 {%0, %1}, %2;" : "=f"(lo), "=f"(hi) : "l"(v));
}
static __device__ __forceinline__ void fma2(unsigned long long& a,
                                            unsigned long long x,
                                            unsigned long long w) {
    asm("fma.rn.f32x2 %0, %1, %2, %0;" : "+l"(a) : "l"(x), "l"(w));
}
static __device__ __forceinline__ float tanh_f(float x) {
    float y;
    asm("tanh.approx.f32 %0, %1;" : "=f"(y) : "f"(x));
    return y;
}
static __device__ __forceinline__ float sig_f(float x) {
    return fmaf(0.5f, tanh_f(0.5f * x), 0.5f);
}

// ======================================================================
// Kernel 1: token table build. table[v][g] = emb[v] . Wih0[g] + b0[g].
// ======================================================================
#define XT_STRIDE 136

__global__ void __launch_bounds__(256, 2)
k_table(const float* __restrict__ emb,
        const float* __restrict__ Wih0,
        const float* __restrict__ bih0,
        const float* __restrict__ bhh0,
        float* __restrict__ tab)
{
    __shared__ float xs[16 * XT_STRIDE];

    const int tid  = threadIdx.x;
    const int gl   = tid >> 1;
    const int half = tid & 1;
    const int g    = blockIdx.y * 128 + gl;

    unsigned long long w[32];
#pragma unroll
    for (int j = 0; j < 16; ++j) {
        ulonglong2 v = *(const ulonglong2*)&Wih0[g * EMB + half * 64 + j * 4];
        w[2 * j] = v.x;  w[2 * j + 1] = v.y;
    }
    const float b0 = (half == 0) ? (__ldg(&bih0[g]) + __ldg(&bhh0[g])) : 0.f;

    const int v0 = blockIdx.x * 128;

#pragma unroll 1
    for (int tile = 0; tile < 8; ++tile) {
        const int vbase = v0 + tile * 16;
        if (vbase >= VOCAB) break;
        const int rows = min(16, VOCAB - vbase);

        __syncthreads();
        for (int j = tid; j < rows * 32; j += 256) {
            const int r = j >> 5, k4 = j & 31;
            const int dst = r * XT_STRIDE + (k4 < 16 ? k4 * 4 : 68 + (k4 - 16) * 4);
            *(float4*)&xs[dst] = *(const float4*)&emb[(size_t)(vbase + r) * EMB + k4 * 4];
        }
        __syncthreads();

        unsigned long long acc[16];
#pragma unroll
        for (int r = 0; r < 16; ++r) acc[r] = pk2(b0, 0.f);

#pragma unroll
        for (int kc = 0; kc < 16; ++kc) {
#pragma unroll
            for (int r = 0; r < 16; ++r) {
                const ulonglong2 x = *(const ulonglong2*)&xs[r * XT_STRIDE + half * 68 + kc * 4];
                fma2(acc[r], x.x, w[2 * kc]);
                fma2(acc[r], x.y, w[2 * kc + 1]);
            }
        }
#pragma unroll
        for (int r = 0; r < 16; ++r) {
            float lo, hi; upk2(acc[r], lo, hi);
            float s = lo + hi;
            s += __shfl_xor_sync(0xFFFFFFFFu, s, 1);
            if (half == 0 && r < rows)
                tab[(size_t)(vbase + r) * GATES + g] = s;
        }
    }
}

// ======================================================================
// Kernel 2: fused 2-layer LSTM scan, layer-pipelined (layer1 lags layer0
// by 1 step), 2 barriers per step. 128 blocks x 512 threads; block owns
// batch rows 4b..4b+3. Thread=(gate g=tid>>1, k-half=tid&1); 96 weight
// regs. xproj prefetched one step ahead via __ldg into registers.
//   prologue: gates0(0)=xproj(0) -> elem0
//   loop t=1..511: [gates1(t-1); gates0(t)] bar [elem0(t)|elem1(t-1)] bar
//   epilogue: gates1(511) -> elem1 -> FC
// ======================================================================
#define HS 136   // h row stride (floats): half0 at +0, half1 at +68

__global__ void __launch_bounds__(512, 1)
k_scan(const int* __restrict__ seq32,
       const float* __restrict__ tab,
       const float* __restrict__ Whh0, const float* __restrict__ Wih1,
       const float* __restrict__ Whh1,
       const float* __restrict__ bih1, const float* __restrict__ bhh1,
       const float* __restrict__ Wfc,  const float* __restrict__ bfc,
       float* __restrict__ out)
{
    __shared__ float h0s[4 * HS];
    __shared__ float h1s[4 * HS];
    __shared__ float gA[4 * GATES * 2];   // layer0 partials [(r*GATES+g)*2+half]
    __shared__ float gB[4 * GATES * 2];   // layer1 partials
    __shared__ int4  tok4[SEQ];           // tokens per step (4 rows)

    const int tid  = threadIdx.x;
    const int g    = tid >> 1;
    const int half = tid & 1;
    const int row0 = blockIdx.x * 4;

    // ---- weights: 3 half-rows of 32 floats -> 48 f32x2 = 96 regs
    unsigned long long w0[16], wi1[16], wh1[16];
#pragma unroll
    for (int j = 0; j < 8; ++j) {
        ulonglong2 v;
        v = *(const ulonglong2*)&Whh0[g * HID + half * 32 + j * 4];
        w0[2 * j] = v.x;  w0[2 * j + 1] = v.y;
        v = *(const ulonglong2*)&Wih1[g * HID + half * 32 + j * 4];
        wi1[2 * j] = v.x; wi1[2 * j + 1] = v.y;
        v = *(const ulonglong2*)&Whh1[g * HID + half * 32 + j * 4];
        wh1[2 * j] = v.x; wh1[2 * j + 1] = v.y;
    }
    const float b1 = (half == 0) ? (__ldg(&bih1[g]) + __ldg(&bhh1[g])) : 0.f;

    // int64 vs int32 input_seq detection
    const bool is64 = ((__ldg(seq32 + 1) | __ldg(seq32 + 3) | __ldg(seq32 + 5) |
                        __ldg(seq32 + 7) | __ldg(seq32 + 9) | __ldg(seq32 + 11) |
                        __ldg(seq32 + 13) | __ldg(seq32 + 15)) == 0);

    // ---- stage tokens (tok4[t] = tokens of the 4 rows at step t)
    {
        const int t = tid;   // SEQ == blockDim == 512
        int4 v;
        if (is64) {
            v.x = __ldg(seq32 + 2 * ((row0 + 0) * SEQ + t));
            v.y = __ldg(seq32 + 2 * ((row0 + 1) * SEQ + t));
            v.z = __ldg(seq32 + 2 * ((row0 + 2) * SEQ + t));
            v.w = __ldg(seq32 + 2 * ((row0 + 3) * SEQ + t));
        } else {
            v.x = __ldg(seq32 + (row0 + 0) * SEQ + t);
            v.y = __ldg(seq32 + (row0 + 1) * SEQ + t);
            v.z = __ldg(seq32 + (row0 + 2) * SEQ + t);
            v.w = __ldg(seq32 + (row0 + 3) * SEQ + t);
        }
        tok4[t] = v;
    }
    for (int j = tid; j < 4 * HS; j += 512) {
        h0s[j] = 0.f;
        h1s[j] = 0.f;
    }

    const int rr = (tid & 255) >> 6;   // elem row (both halves of the block)
    const int u  = tid & 63;
    float c0 = 0.f, c1 = 0.f;

    __syncthreads();   // tok4 / h ready

    // ---- xproj(0) and prefetch xproj(1) (half0 only)
    float x0 = 0.f, x1 = 0.f, x2 = 0.f, x3 = 0.f;
    float p0 = 0.f, p1 = 0.f, p2 = 0.f, p3 = 0.f;
    if (half == 0) {
        int4 tk = tok4[0];
        x0 = __ldg(&tab[(size_t)tk.x * GATES + g]);
        x1 = __ldg(&tab[(size_t)tk.y * GATES + g]);
        x2 = __ldg(&tab[(size_t)tk.z * GATES + g]);
        x3 = __ldg(&tab[(size_t)tk.w * GATES + g]);
        tk = tok4[1];
        p0 = __ldg(&tab[(size_t)tk.x * GATES + g]);
        p1 = __ldg(&tab[(size_t)tk.y * GATES + g]);
        p2 = __ldg(&tab[(size_t)tk.z * GATES + g]);
        p3 = __ldg(&tab[(size_t)tk.w * GATES + g]);
    }

    // ---- prologue t=0: gates0(0) = xproj(0) (h0(-1)=0)
    {
        const int gi = (0 * GATES + g) * 2 + half;
        gA[gi]        = half ? 0.f : x0;
        gA[gi + 512]  = half ? 0.f : x1;
        gA[gi + 1024] = half ? 0.f : x2;
        gA[gi + 1536] = half ? 0.f : x3;
    }
    __syncthreads();
    if (tid < 256) {
        const float2* gr = (const float2*)(gA + rr * GATES * 2);
        const float2 vi = gr[u],       vf = gr[64 + u];
        const float2 vg = gr[128 + u], vo = gr[192 + u];
        float i_ = sig_f(vi.x + vi.y);
        float f_ = sig_f(vf.x + vf.y);
        float g_ = tanh_f(vg.x + vg.y);
        float o_ = sig_f(vo.x + vo.y);
        c0 = f_ * 0.f + i_ * g_;
        h0s[rr * HS + (u >> 5) * 68 + (u & 31)] = o_ * tanh_f(c0);
    }
    __syncthreads();
    x0 = p0; x1 = p1; x2 = p2; x3 = p3;

    // ======== steady state: t = 1 .. SEQ-1 ========
#pragma unroll 1
    for (int t = 1; t < SEQ; ++t) {
        // prefetch xproj(t+1)
        if (half == 0 && t + 1 < SEQ) {
            const int4 tk = tok4[t + 1];
            p0 = __ldg(&tab[(size_t)tk.x * GATES + g]);
            p1 = __ldg(&tab[(size_t)tk.y * GATES + g]);
            p2 = __ldg(&tab[(size_t)tk.z * GATES + g]);
            p3 = __ldg(&tab[(size_t)tk.w * GATES + g]);
        }

        // ---- gates1(t-1) = b1 + h0(t-1)·Wih1 + h1(t-2)·Whh1
        {
            unsigned long long a[4];
#pragma unroll
            for (int r = 0; r < 4; ++r) a[r] = pk2(b1, 0.f);
#pragma unroll
            for (int kc = 0; kc < 8; ++kc) {
#pragma unroll
                for (int r = 0; r < 4; ++r) {
                    const ulonglong2 h0v = *(const ulonglong2*)&h0s[r * HS + half * 68 + kc * 4];
                    fma2(a[r], h0v.x, wi1[2 * kc]);
                    fma2(a[r], h0v.y, wi1[2 * kc + 1]);
                    const ulonglong2 h1v = *(const ulonglong2*)&h1s[r * HS + half * 68 + kc * 4];
                    fma2(a[r], h1v.x, wh1[2 * kc]);
                    fma2(a[r], h1v.y, wh1[2 * kc + 1]);
                }
            }
#pragma unroll
            for (int r = 0; r < 4; ++r) {
                float lo, hi; upk2(a[r], lo, hi);
                gB[(r * GATES + g) * 2 + half] = lo + hi;
            }
        }
        // ---- gates0(t) = xproj(t) + h0(t-1)·Whh0
        {
            unsigned long long a[4];
            a[0] = pk2(x0, 0.f); a[1] = pk2(x1, 0.f);
            a[2] = pk2(x2, 0.f); a[3] = pk2(x3, 0.f);
#pragma unroll
            for (int kc = 0; kc < 8; ++kc) {
#pragma unroll
                for (int r = 0; r < 4; ++r) {
                    const ulonglong2 h = *(const ulonglong2*)&h0s[r * HS + half * 68 + kc * 4];
                    fma2(a[r], h.x, w0[2 * kc]);
                    fma2(a[r], h.y, w0[2 * kc + 1]);
                }
            }
#pragma unroll
            for (int r = 0; r < 4; ++r) {
                float lo, hi; upk2(a[r], lo, hi);
                gA[(r * GATES + g) * 2 + half] = lo + hi;
            }
        }
        __syncthreads();   // (1) gA/gB ready; h reads complete

        // ---- fused elementwise: tid<256 layer0(t); tid>=256 layer1(t-1)
        {
            const float* gbase = (tid < 256) ? gA : gB;
            const float2* gr = (const float2*)(gbase + rr * GATES * 2);
            const float2 vi = gr[u],       vf = gr[64 + u];
            const float2 vg = gr[128 + u], vo = gr[192 + u];
            float i_ = sig_f(vi.x + vi.y);
            float f_ = sig_f(vf.x + vf.y);
            float g_ = tanh_f(vg.x + vg.y);
            float o_ = sig_f(vo.x + vo.y);
            if (tid < 256) {
                c0 = f_ * c0 + i_ * g_;
                h0s[rr * HS + (u >> 5) * 68 + (u & 31)] = o_ * tanh_f(c0);
            } else {
                c1 = f_ * c1 + i_ * g_;
                h1s[rr * HS + (u >> 5) * 68 + (u & 31)] = o_ * tanh_f(c1);
            }
        }
        __syncthreads();   // (2) h0(t), h1(t-1) published

        x0 = p0; x1 = p1; x2 = p2; x3 = p3;
    }

    // ======== epilogue: gates1(511) -> h1(511) ========
    {
        unsigned long long a[4];
#pragma unroll
        for (int r = 0; r < 4; ++r) a[r] = pk2(b1, 0.f);
#pragma unroll
        for (int kc = 0; kc < 8; ++kc) {
#pragma unroll
            for (int r = 0; r < 4; ++r) {
                const ulonglong2 h0v = *(const ulonglong2*)&h0s[r * HS + half * 68 + kc * 4];
                fma2(a[r], h0v.x, wi1[2 * kc]);
                fma2(a[r], h0v.y, wi1[2 * kc + 1]);
                const ulonglong2 h1v = *(const ulonglong2*)&h1s[r * HS + half * 68 + kc * 4];
                fma2(a[r], h1v.x, wh1[2 * kc]);
                fma2(a[r], h1v.y, wh1[2 * kc + 1]);
            }
        }
#pragma unroll
        for (int r = 0; r < 4; ++r) {
            float lo, hi; upk2(a[r], lo, hi);
            gB[(r * GATES + g) * 2 + half] = lo + hi;
        }
    }
    __syncthreads();
    if (tid >= 256) {
        const float2* gr = (const float2*)(gB + rr * GATES * 2);
        const float2 vi = gr[u],       vf = gr[64 + u];
        const float2 vg = gr[128 + u], vo = gr[192 + u];
        float i_ = sig_f(vi.x + vi.y);
        float f_ = sig_f(vf.x + vf.y);
        float g_ = tanh_f(vg.x + vg.y);
        float o_ = sig_f(vo.x + vo.y);
        c1 = f_ * c1 + i_ * g_;
        h1s[rr * HS + (u >> 5) * 68 + (u & 31)] = o_ * tanh_f(c1);
    }
    __syncthreads();

    // ---- Final FC + sigmoid on h1(511)
    if (tid < 8) {
        int r = tid >> 1, o = tid & 1;
        float a = __ldg(&bfc[o]);
        for (int k = 0; k < HID; ++k)
            a = fmaf(h1s[r * HS + (k >> 5) * 68 + (k & 31)],
                     __ldg(&Wfc[o * HID + k]), a);
        out[(row0 + r) * 2 + o] = sig_f(a);
    }
}

// ======================================================================
extern "C" void kernel_launch(void* const* d_in, const int* in_sizes, int n_in,
                              void* d_out, int out_size) {
    const int*   seq32 = (const int*)d_in[0];
    const float* emb   = (const float*)d_in[1];
    const float* Wih0  = (const float*)d_in[2];
    const float* Whh0  = (const float*)d_in[3];
    const float* bih0  = (const float*)d_in[4];
    const float* bhh0  = (const float*)d_in[5];
    const float* Wih1  = (const float*)d_in[6];
    const float* Whh1  = (const float*)d_in[7];
    const float* bih1  = (const float*)d_in[8];
    const float* bhh1  = (const float*)d_in[9];
    const float* Wfc   = (const float*)d_in[10];
    const float* bfc   = (const float*)d_in[11];
    float* out = (float*)d_out;

    float* tab = nullptr;
    cudaGetSymbolAddress((void**)&tab, g_tab);

    dim3 gtab((VOCAB + 127) / 128, 2);
    k_table<<<gtab, 256>>>(emb, Wih0, bih0, bhh0, tab);
    k_scan<<<BATCH / 4, 512>>>(seq32, tab, Whh0, Wih1, Whh1,
                               bih1, bhh1, Wfc, bfc, out);
}

// round 7
// speedup vs baseline: 2.2459x; 2.2459x over previous
#include <cuda_runtime.h>
#include <cstdint>

#define BATCH 512
#define SEQ   512
#define EMB   128
#define HID   64
#define GATES 256   // 4*HID
#define VOCAB 50000

// 51.2 MB token->xproj table: table[v][g] = dot(emb[v], Wih0[g]) + bih0[g] + bhh0[g]
__device__ float g_tab[(size_t)VOCAB * GATES];

// ---------------- packed f32x2 helpers ----------------
static __device__ __forceinline__ unsigned long long pk2(float lo, float hi) {
    unsigned long long v;
    asm("mov.b64 %0, {%1, %2};" : "=l"(v) : "f"(lo), "f"(hi));
    return v;
}
static __device__ __forceinline__ void upk2(unsigned long long v, float& lo, float& hi) {
    asm("mov.b64 {%0, %1}, %2;" : "=f"(lo), "=f"(hi) : "l"(v));
}
static __device__ __forceinline__ void fma2(unsigned long long& a,
                                            unsigned long long x,
                                            unsigned long long w) {
    asm("fma.rn.f32x2 %0, %1, %2, %0;" : "+l"(a) : "l"(x), "l"(w));
}
static __device__ __forceinline__ float tanh_f(float x) {
    float y;
    asm("tanh.approx.f32 %0, %1;" : "=f"(y) : "f"(x));
    return y;
}
static __device__ __forceinline__ float sig_f(float x) {
    return fmaf(0.5f, tanh_f(0.5f * x), 0.5f);
}

// ======================================================================
// Kernel 1: token table build. table[v][g] = emb[v] . Wih0[g] + b0[g].
// ======================================================================
#define XT_STRIDE 136

__global__ void __launch_bounds__(256, 2)
k_table(const float* __restrict__ emb,
        const float* __restrict__ Wih0,
        const float* __restrict__ bih0,
        const float* __restrict__ bhh0,
        float* __restrict__ tab)
{
    __shared__ float xs[16 * XT_STRIDE];

    const int tid  = threadIdx.x;
    const int gl   = tid >> 1;
    const int half = tid & 1;
    const int g    = blockIdx.y * 128 + gl;

    unsigned long long w[32];
#pragma unroll
    for (int j = 0; j < 16; ++j) {
        ulonglong2 v = *(const ulonglong2*)&Wih0[g * EMB + half * 64 + j * 4];
        w[2 * j] = v.x;  w[2 * j + 1] = v.y;
    }
    const float b0 = (half == 0) ? (__ldg(&bih0[g]) + __ldg(&bhh0[g])) : 0.f;

    const int v0 = blockIdx.x * 128;

#pragma unroll 1
    for (int tile = 0; tile < 8; ++tile) {
        const int vbase = v0 + tile * 16;
        if (vbase >= VOCAB) break;
        const int rows = min(16, VOCAB - vbase);

        __syncthreads();
        for (int j = tid; j < rows * 32; j += 256) {
            const int r = j >> 5, k4 = j & 31;
            const int dst = r * XT_STRIDE + (k4 < 16 ? k4 * 4 : 68 + (k4 - 16) * 4);
            *(float4*)&xs[dst] = *(const float4*)&emb[(size_t)(vbase + r) * EMB + k4 * 4];
        }
        __syncthreads();

        unsigned long long acc[16];
#pragma unroll
        for (int r = 0; r < 16; ++r) acc[r] = pk2(b0, 0.f);

#pragma unroll
        for (int kc = 0; kc < 16; ++kc) {
#pragma unroll
            for (int r = 0; r < 16; ++r) {
                const ulonglong2 x = *(const ulonglong2*)&xs[r * XT_STRIDE + half * 68 + kc * 4];
                fma2(acc[r], x.x, w[2 * kc]);
                fma2(acc[r], x.y, w[2 * kc + 1]);
            }
        }
#pragma unroll
        for (int r = 0; r < 16; ++r) {
            float lo, hi; upk2(acc[r], lo, hi);
            float s = lo + hi;
            s += __shfl_xor_sync(0xFFFFFFFFu, s, 1);
            if (half == 0 && r < rows)
                tab[(size_t)(vbase + r) * GATES + g] = s;
        }
    }
}

// ======================================================================
// Kernel 2: fused 2-layer LSTM scan, layer-pipelined (layer1 lags layer0
// by one step), 2 barriers per step. 128 blocks x 256 threads; block owns
// batch rows 4b..4b+3. Thread = gate g = tid: holds FULL 64-float rows of
// Whh0 / Wih1 / Whh1 in registers (192 regs) -- proven non-spilling shape
// (R2: 254 regs). Accumulator blocks are SEQUENTIAL, reusing one a[4].
// Elementwise: each thread updates its (row,unit) for BOTH layers.
//   prologue: gates0(0)=xproj(0) -> elem0
//   loop t=1..511: [gates1(t-1); gates0(t)] bar [elem0(t)+elem1(t-1)] bar
//   epilogue: gates1(511) -> elem1 -> FC
// ======================================================================
#define HS 68   // h row stride (floats)

__global__ void __launch_bounds__(256, 1)
k_scan(const int* __restrict__ seq32,
       const float* __restrict__ tab,
       const float* __restrict__ Whh0, const float* __restrict__ Wih1,
       const float* __restrict__ Whh1,
       const float* __restrict__ bih1, const float* __restrict__ bhh1,
       const float* __restrict__ Wfc,  const float* __restrict__ bfc,
       float* __restrict__ out)
{
    __shared__ float h0s[4 * HS];
    __shared__ float h1s[4 * HS];
    __shared__ float gA[4 * GATES];   // layer0 gate exchange [r*GATES+g]
    __shared__ float gB[4 * GATES];   // layer1 gate exchange
    __shared__ int4  tok4[SEQ];       // tokens per step (4 rows)

    const int tid  = threadIdx.x;
    const int g    = tid;             // gate index
    const int row0 = blockIdx.x * 4;

    // ---- weights: 3 full rows of 64 floats -> 96 f32x2 = 192 regs
    unsigned long long w0[32], wi1[32], wh1[32];
#pragma unroll
    for (int j = 0; j < 16; ++j) {
        ulonglong2 v;
        v = *(const ulonglong2*)&Whh0[g * HID + j * 4];
        w0[2 * j] = v.x;  w0[2 * j + 1] = v.y;
        v = *(const ulonglong2*)&Wih1[g * HID + j * 4];
        wi1[2 * j] = v.x; wi1[2 * j + 1] = v.y;
        v = *(const ulonglong2*)&Whh1[g * HID + j * 4];
        wh1[2 * j] = v.x; wh1[2 * j + 1] = v.y;
    }
    const float b1 = __ldg(&bih1[g]) + __ldg(&bhh1[g]);

    // int64 vs int32 input_seq detection
    const bool is64 = ((__ldg(seq32 + 1) | __ldg(seq32 + 3) | __ldg(seq32 + 5) |
                        __ldg(seq32 + 7) | __ldg(seq32 + 9) | __ldg(seq32 + 11) |
                        __ldg(seq32 + 13) | __ldg(seq32 + 15)) == 0);

    // ---- stage tokens (tok4[t] = tokens of the 4 rows at step t)
    for (int t = tid; t < SEQ; t += 256) {
        int4 v;
        if (is64) {
            v.x = __ldg(seq32 + 2 * ((row0 + 0) * SEQ + t));
            v.y = __ldg(seq32 + 2 * ((row0 + 1) * SEQ + t));
            v.z = __ldg(seq32 + 2 * ((row0 + 2) * SEQ + t));
            v.w = __ldg(seq32 + 2 * ((row0 + 3) * SEQ + t));
        } else {
            v.x = __ldg(seq32 + (row0 + 0) * SEQ + t);
            v.y = __ldg(seq32 + (row0 + 1) * SEQ + t);
            v.z = __ldg(seq32 + (row0 + 2) * SEQ + t);
            v.w = __ldg(seq32 + (row0 + 3) * SEQ + t);
        }
        tok4[t] = v;
    }
    for (int j = tid; j < 4 * HS; j += 256) {
        h0s[j] = 0.f;
        h1s[j] = 0.f;
    }

    const int rr = tid >> 6;       // elem row
    const int u  = tid & 63;       // elem unit
    float c0 = 0.f, c1 = 0.f;

    __syncthreads();   // tok4 / h ready

    // ---- xproj(0) and prefetch xproj(1)
    float x0, x1, x2, x3, p0, p1, p2, p3;
    {
        int4 tk = tok4[0];
        x0 = __ldg(&tab[(size_t)tk.x * GATES + g]);
        x1 = __ldg(&tab[(size_t)tk.y * GATES + g]);
        x2 = __ldg(&tab[(size_t)tk.z * GATES + g]);
        x3 = __ldg(&tab[(size_t)tk.w * GATES + g]);
        tk = tok4[1];
        p0 = __ldg(&tab[(size_t)tk.x * GATES + g]);
        p1 = __ldg(&tab[(size_t)tk.y * GATES + g]);
        p2 = __ldg(&tab[(size_t)tk.z * GATES + g]);
        p3 = __ldg(&tab[(size_t)tk.w * GATES + g]);
    }

    // ---- prologue t=0: gates0(0) = xproj(0) (h0(-1)=0)
    gA[0 * GATES + g] = x0;
    gA[1 * GATES + g] = x1;
    gA[2 * GATES + g] = x2;
    gA[3 * GATES + g] = x3;
    __syncthreads();
    {
        const float* gr = gA + rr * GATES;
        float i_ = sig_f(gr[u]);
        float g_ = tanh_f(gr[128 + u]);
        float o_ = sig_f(gr[192 + u]);
        c0 = i_ * g_;
        h0s[rr * HS + u] = o_ * tanh_f(c0);
    }
    __syncthreads();
    x0 = p0; x1 = p1; x2 = p2; x3 = p3;

    // ======== steady state: t = 1 .. SEQ-1 ========
#pragma unroll 1
    for (int t = 1; t < SEQ; ++t) {
        // prefetch xproj(t+1) (one full step of latency cover)
        if (t + 1 < SEQ) {
            const int4 tk = tok4[t + 1];
            p0 = __ldg(&tab[(size_t)tk.x * GATES + g]);
            p1 = __ldg(&tab[(size_t)tk.y * GATES + g]);
            p2 = __ldg(&tab[(size_t)tk.z * GATES + g]);
            p3 = __ldg(&tab[(size_t)tk.w * GATES + g]);
        }

        {
            // ---- gates1(t-1) = b1 + h0(t-1)·Wih1 + h1(t-2)·Whh1
            unsigned long long a[4];
#pragma unroll
            for (int r = 0; r < 4; ++r) a[r] = pk2(b1, 0.f);
#pragma unroll
            for (int kc = 0; kc < 16; ++kc) {
#pragma unroll
                for (int r = 0; r < 4; ++r) {
                    const ulonglong2 h0v = *(const ulonglong2*)&h0s[r * HS + kc * 4];
                    fma2(a[r], h0v.x, wi1[2 * kc]);
                    fma2(a[r], h0v.y, wi1[2 * kc + 1]);
                    const ulonglong2 h1v = *(const ulonglong2*)&h1s[r * HS + kc * 4];
                    fma2(a[r], h1v.x, wh1[2 * kc]);
                    fma2(a[r], h1v.y, wh1[2 * kc + 1]);
                }
            }
#pragma unroll
            for (int r = 0; r < 4; ++r) {
                float lo, hi; upk2(a[r], lo, hi);
                gB[r * GATES + g] = lo + hi;
            }
        }
        {
            // ---- gates0(t) = xproj(t) + h0(t-1)·Whh0
            unsigned long long a[4];
            a[0] = pk2(x0, 0.f); a[1] = pk2(x1, 0.f);
            a[2] = pk2(x2, 0.f); a[3] = pk2(x3, 0.f);
#pragma unroll
            for (int kc = 0; kc < 16; ++kc) {
#pragma unroll
                for (int r = 0; r < 4; ++r) {
                    const ulonglong2 h = *(const ulonglong2*)&h0s[r * HS + kc * 4];
                    fma2(a[r], h.x, w0[2 * kc]);
                    fma2(a[r], h.y, w0[2 * kc + 1]);
                }
            }
#pragma unroll
            for (int r = 0; r < 4; ++r) {
                float lo, hi; upk2(a[r], lo, hi);
                gA[r * GATES + g] = lo + hi;
            }
        }
        __syncthreads();   // (1) gA/gB ready; h reads complete

        // ---- fused elementwise: this thread's (rr,u) for BOTH layers
        {
            const float* gr = gA + rr * GATES;
            float i_ = sig_f(gr[u]);
            float f_ = sig_f(gr[64 + u]);
            float g_ = tanh_f(gr[128 + u]);
            float o_ = sig_f(gr[192 + u]);
            c0 = f_ * c0 + i_ * g_;
            h0s[rr * HS + u] = o_ * tanh_f(c0);
        }
        {
            const float* gr = gB + rr * GATES;
            float i_ = sig_f(gr[u]);
            float f_ = sig_f(gr[64 + u]);
            float g_ = tanh_f(gr[128 + u]);
            float o_ = sig_f(gr[192 + u]);
            c1 = f_ * c1 + i_ * g_;
            h1s[rr * HS + u] = o_ * tanh_f(c1);
        }
        __syncthreads();   // (2) h0(t), h1(t-1) published

        x0 = p0; x1 = p1; x2 = p2; x3 = p3;
    }

    // ======== epilogue: gates1(511) -> h1(511) ========
    {
        unsigned long long a[4];
#pragma unroll
        for (int r = 0; r < 4; ++r) a[r] = pk2(b1, 0.f);
#pragma unroll
        for (int kc = 0; kc < 16; ++kc) {
#pragma unroll
            for (int r = 0; r < 4; ++r) {
                const ulonglong2 h0v = *(const ulonglong2*)&h0s[r * HS + kc * 4];
                fma2(a[r], h0v.x, wi1[2 * kc]);
                fma2(a[r], h0v.y, wi1[2 * kc + 1]);
                const ulonglong2 h1v = *(const ulonglong2*)&h1s[r * HS + kc * 4];
                fma2(a[r], h1v.x, wh1[2 * kc]);
                fma2(a[r], h1v.y, wh1[2 * kc + 1]);
            }
        }
#pragma unroll
        for (int r = 0; r < 4; ++r) {
            float lo, hi; upk2(a[r], lo, hi);
            gB[r * GATES + g] = lo + hi;
        }
    }
    __syncthreads();
    {
        const float* gr = gB + rr * GATES;
        float i_ = sig_f(gr[u]);
        float f_ = sig_f(gr[64 + u]);
        float g_ = tanh_f(gr[128 + u]);
        float o_ = sig_f(gr[192 + u]);
        c1 = f_ * c1 + i_ * g_;
        h1s[rr * HS + u] = o_ * tanh_f(c1);
    }
    __syncthreads();

    // ---- Final FC + sigmoid on h1(511)
    if (tid < 8) {
        int r = tid >> 1, o = tid & 1;
        float a = __ldg(&bfc[o]);
        for (int k = 0; k < HID; ++k)
            a = fmaf(h1s[r * HS + k], __ldg(&Wfc[o * HID + k]), a);
        out[(row0 + r) * 2 + o] = sig_f(a);
    }
}

// ======================================================================
extern "C" void kernel_launch(void* const* d_in, const int* in_sizes, int n_in,
                              void* d_out, int out_size) {
    const int*   seq32 = (const int*)d_in[0];
    const float* emb   = (const float*)d_in[1];
    const float* Wih0  = (const float*)d_in[2];
    const float* Whh0  = (const float*)d_in[3];
    const float* bih0  = (const float*)d_in[4];
    const float* bhh0  = (const float*)d_in[5];
    const float* Wih1  = (const float*)d_in[6];
    const float* Whh1  = (const float*)d_in[7];
    const float* bih1  = (const float*)d_in[8];
    const float* bhh1  = (const float*)d_in[9];
    const float* Wfc   = (const float*)d_in[10];
    const float* bfc   = (const float*)d_in[11];
    float* out = (float*)d_out;

    float* tab = nullptr;
    cudaGetSymbolAddress((void**)&tab, g_tab);

    dim3 gtab((VOCAB + 127) / 128, 2);
    k_table<<<gtab, 256>>>(emb, Wih0, bih0, bhh0, tab);
    k_scan<<<BATCH / 4, 256>>>(seq32, tab, Whh0, Wih1, Whh1,
                               bih1, bhh1, Wfc, bfc, out);
}

// round 8
// speedup vs baseline: 6.7528x; 3.0067x over previous
#include <cuda_runtime.h>
#include <cstdint>

#define BATCH 512
#define SEQ   512
#define EMB   128
#define HID   64
#define GATES 256   // 4*HID
#define VOCAB 50000

// 51.2 MB token->xproj table: table[v][g] = dot(emb[v], Wih0[g]) + bih0[g] + bhh0[g]
__device__ float g_tab[(size_t)VOCAB * GATES];

// ---------------- packed f32x2 helpers ----------------
static __device__ __forceinline__ unsigned long long pk2(float lo, float hi) {
    unsigned long long v;
    asm("mov.b64 %0, {%1, %2};" : "=l"(v) : "f"(lo), "f"(hi));
    return v;
}
static __device__ __forceinline__ void upk2(unsigned long long v, float& lo, float& hi) {
    asm("mov.b64 {%0, %1}, %2;" : "=f"(lo), "=f"(hi) : "l"(v));
}
static __device__ __forceinline__ void fma2(unsigned long long& a,
                                            unsigned long long x,
                                            unsigned long long w) {
    asm("fma.rn.f32x2 %0, %1, %2, %0;" : "+l"(a) : "l"(x), "l"(w));
}
static __device__ __forceinline__ float tanh_f(float x) {
    float y;
    asm("tanh.approx.f32 %0, %1;" : "=f"(y) : "f"(x));
    return y;
}
static __device__ __forceinline__ float sig_f(float x) {
    return fmaf(0.5f, tanh_f(0.5f * x), 0.5f);
}

// ======================================================================
// Kernel 1: token table build. table[v][g] = emb[v] . Wih0[g] + b0[g].
// ======================================================================
#define XT_STRIDE 136

__global__ void __launch_bounds__(256, 2)
k_table(const float* __restrict__ emb,
        const float* __restrict__ Wih0,
        const float* __restrict__ bih0,
        const float* __restrict__ bhh0,
        float* __restrict__ tab)
{
    __shared__ float xs[16 * XT_STRIDE];

    const int tid  = threadIdx.x;
    const int gl   = tid >> 1;
    const int half = tid & 1;
    const int g    = blockIdx.y * 128 + gl;

    unsigned long long w[32];
#pragma unroll
    for (int j = 0; j < 16; ++j) {
        ulonglong2 v = *(const ulonglong2*)&Wih0[g * EMB + half * 64 + j * 4];
        w[2 * j] = v.x;  w[2 * j + 1] = v.y;
    }
    const float b0 = (half == 0) ? (__ldg(&bih0[g]) + __ldg(&bhh0[g])) : 0.f;

    const int v0 = blockIdx.x * 128;

#pragma unroll 1
    for (int tile = 0; tile < 8; ++tile) {
        const int vbase = v0 + tile * 16;
        if (vbase >= VOCAB) break;
        const int rows = min(16, VOCAB - vbase);

        __syncthreads();
        for (int j = tid; j < rows * 32; j += 256) {
            const int r = j >> 5, k4 = j & 31;
            const int dst = r * XT_STRIDE + (k4 < 16 ? k4 * 4 : 68 + (k4 - 16) * 4);
            *(float4*)&xs[dst] = *(const float4*)&emb[(size_t)(vbase + r) * EMB + k4 * 4];
        }
        __syncthreads();

        unsigned long long acc[16];
#pragma unroll
        for (int r = 0; r < 16; ++r) acc[r] = pk2(b0, 0.f);

#pragma unroll
        for (int kc = 0; kc < 16; ++kc) {
#pragma unroll
            for (int r = 0; r < 16; ++r) {
                const ulonglong2 x = *(const ulonglong2*)&xs[r * XT_STRIDE + half * 68 + kc * 4];
                fma2(acc[r], x.x, w[2 * kc]);
                fma2(acc[r], x.y, w[2 * kc + 1]);
            }
        }
#pragma unroll
        for (int r = 0; r < 16; ++r) {
            float lo, hi; upk2(acc[r], lo, hi);
            float s = lo + hi;
            s += __shfl_xor_sync(0xFFFFFFFFu, s, 1);
            if (half == 0 && r < rows)
                tab[(size_t)(vbase + r) * GATES + g] = s;
        }
    }
}

// ======================================================================
// Kernel 2: fused 2-layer LSTM scan + FC. PROVEN R2 dataflow (3 barriers,
// double-buffered h, thread = gate), with reduced register footprint:
//   - Whh0, Wih1 rows in registers (128 regs)
//   - Whh1 rows in padded smem (stride 68; conflict-free LDS.128)
//   - xproj gathered from the token table (tok4 staged in smem),
//     one-step register prefetch.
// 128 blocks x 256 threads; block owns batch rows 4b..4b+3.
// Per step: A gates0 | bar | B elem0 | bar | C gates1 | bar | D elem1.
// ======================================================================
#define WS 68   // wh1 smem row stride (floats); conflict-free for LDS.128

__global__ void __launch_bounds__(256, 1)
k_scan(const int* __restrict__ seq32,
       const float* __restrict__ tab,
       const float* __restrict__ Whh0, const float* __restrict__ Wih1,
       const float* __restrict__ Whh1,
       const float* __restrict__ bih1, const float* __restrict__ bhh1,
       const float* __restrict__ Wfc,  const float* __restrict__ bfc,
       float* __restrict__ out)
{
    extern __shared__ float sm[];
    float* wh1s = sm;                      // 256*68 = 17408
    float* h0s  = wh1s + 256 * WS;         // 2 buffers * 256
    float* h1s  = h0s + 512;               // 2 buffers * 256
    float* gA   = h1s + 512;               // 1024
    float* gB   = gA + 1024;               // 1024
    int4*  tok4 = (int4*)(gB + 1024);      // SEQ int4

    const int tid  = threadIdx.x;
    const int g    = tid;                  // gate index
    const int row0 = blockIdx.x * 4;

    // ---- weights: Whh0 + Wih1 rows in registers (64 f32x2 = 128 regs)
    unsigned long long w0[32], wi1[32];
#pragma unroll
    for (int j = 0; j < 16; ++j) {
        ulonglong2 v;
        v = *(const ulonglong2*)&Whh0[g * HID + j * 4];
        w0[2 * j] = v.x;  w0[2 * j + 1] = v.y;
        v = *(const ulonglong2*)&Wih1[g * HID + j * 4];
        wi1[2 * j] = v.x; wi1[2 * j + 1] = v.y;
    }
    // ---- Whh1 into padded smem
    for (int j = tid; j < 256 * HID; j += 256)
        wh1s[(j >> 6) * WS + (j & 63)] = Whh1[j];

    const float b1 = __ldg(&bih1[g]) + __ldg(&bhh1[g]);

    // int64 vs int32 input_seq detection
    const bool is64 = ((__ldg(seq32 + 1) | __ldg(seq32 + 3) | __ldg(seq32 + 5) |
                        __ldg(seq32 + 7) | __ldg(seq32 + 9) | __ldg(seq32 + 11) |
                        __ldg(seq32 + 13) | __ldg(seq32 + 15)) == 0);

    // ---- stage tokens (tok4[t] = tokens of the 4 rows at step t)
    for (int t = tid; t < SEQ; t += 256) {
        int4 v;
        if (is64) {
            v.x = __ldg(seq32 + 2 * ((row0 + 0) * SEQ + t));
            v.y = __ldg(seq32 + 2 * ((row0 + 1) * SEQ + t));
            v.z = __ldg(seq32 + 2 * ((row0 + 2) * SEQ + t));
            v.w = __ldg(seq32 + 2 * ((row0 + 3) * SEQ + t));
        } else {
            v.x = __ldg(seq32 + (row0 + 0) * SEQ + t);
            v.y = __ldg(seq32 + (row0 + 1) * SEQ + t);
            v.z = __ldg(seq32 + (row0 + 2) * SEQ + t);
            v.w = __ldg(seq32 + (row0 + 3) * SEQ + t);
        }
        tok4[t] = v;
    }
    // zero h buffers (buffer 0 = state at t=-1)
    for (int j = tid; j < 512; j += 256) {
        h0s[j] = 0.f;
        h1s[j] = 0.f;
    }

    const int rr = tid >> 6;       // elem row
    const int u  = tid & 63;       // elem unit
    float c0 = 0.f, c1 = 0.f;

    __syncthreads();   // tok4 / wh1s / h ready

    // ---- xproj(0) and prefetch xproj(1)
    float x0, x1, x2, x3, p0, p1, p2, p3;
    {
        int4 tk = tok4[0];
        x0 = __ldg(&tab[(size_t)tk.x * GATES + g]);
        x1 = __ldg(&tab[(size_t)tk.y * GATES + g]);
        x2 = __ldg(&tab[(size_t)tk.z * GATES + g]);
        x3 = __ldg(&tab[(size_t)tk.w * GATES + g]);
        tk = tok4[1];
        p0 = __ldg(&tab[(size_t)tk.x * GATES + g]);
        p1 = __ldg(&tab[(size_t)tk.y * GATES + g]);
        p2 = __ldg(&tab[(size_t)tk.z * GATES + g]);
        p3 = __ldg(&tab[(size_t)tk.w * GATES + g]);
    }

#pragma unroll 1
    for (int t = 0; t < SEQ; ++t) {
        const int cur = (t & 1) * 256, nxt = 256 - cur;

        // ---- Phase A: gates0(t) = xproj(t) + h0(t-1)·Whh0
        {
            unsigned long long a[4];
            a[0] = pk2(x0, 0.f); a[1] = pk2(x1, 0.f);
            a[2] = pk2(x2, 0.f); a[3] = pk2(x3, 0.f);
#pragma unroll
            for (int kc = 0; kc < 16; ++kc) {
#pragma unroll
                for (int r = 0; r < 4; ++r) {
                    const ulonglong2 h = *(const ulonglong2*)&h0s[cur + r * HID + kc * 4];
                    fma2(a[r], h.x, w0[2 * kc]);
                    fma2(a[r], h.y, w0[2 * kc + 1]);
                }
            }
#pragma unroll
            for (int r = 0; r < 4; ++r) {
                float lo, hi; upk2(a[r], lo, hi);
                gA[r * GATES + g] = lo + hi;
            }
        }
        // prefetch xproj(t+1) -> registers (issued here, consumed next iter)
        if (t + 1 < SEQ) {
            const int4 tk = tok4[t + 1];
            p0 = __ldg(&tab[(size_t)tk.x * GATES + g]);
            p1 = __ldg(&tab[(size_t)tk.y * GATES + g]);
            p2 = __ldg(&tab[(size_t)tk.z * GATES + g]);
            p3 = __ldg(&tab[(size_t)tk.w * GATES + g]);
        }
        __syncthreads();   // (1) gA ready

        // ---- Phase B: layer0 elementwise -> h0(t) into nxt buffer
        {
            const float* gr = gA + rr * GATES;
            float i_ = sig_f(gr[u]);
            float f_ = sig_f(gr[64 + u]);
            float g_ = tanh_f(gr[128 + u]);
            float o_ = sig_f(gr[192 + u]);
            c0 = f_ * c0 + i_ * g_;
            h0s[nxt + rr * HID + u] = o_ * tanh_f(c0);
        }
        __syncthreads();   // (2) h0(t) ready

        // ---- Phase C: gates1(t) = b1 + h0(t)·Wih1(regs) + h1(t-1)·Whh1(smem)
        {
            unsigned long long a[4];
#pragma unroll
            for (int r = 0; r < 4; ++r) a[r] = pk2(b1, 0.f);
#pragma unroll
            for (int kc = 0; kc < 16; ++kc) {
                const ulonglong2 wv = *(const ulonglong2*)&wh1s[g * WS + kc * 4];
#pragma unroll
                for (int r = 0; r < 4; ++r) {
                    const ulonglong2 h0v = *(const ulonglong2*)&h0s[nxt + r * HID + kc * 4];
                    fma2(a[r], h0v.x, wi1[2 * kc]);
                    fma2(a[r], h0v.y, wi1[2 * kc + 1]);
                    const ulonglong2 h1v = *(const ulonglong2*)&h1s[cur + r * HID + kc * 4];
                    fma2(a[r], h1v.x, wv.x);
                    fma2(a[r], h1v.y, wv.y);
                }
            }
#pragma unroll
            for (int r = 0; r < 4; ++r) {
                float lo, hi; upk2(a[r], lo, hi);
                gB[r * GATES + g] = lo + hi;
            }
        }
        __syncthreads();   // (3) gB ready

        // ---- Phase D: layer1 elementwise -> h1(t) into nxt buffer
        // (no trailing barrier: next step's barrier (1) orders h1/gB reuse;
        //  phase A reads only h0[cur]=this step's nxt... h0 was written in B
        //  of this step into nxt, which becomes cur next step -- ordered by
        //  barrier (2)+(3).)
        {
            const float* gr = gB + rr * GATES;
            float i_ = sig_f(gr[u]);
            float f_ = sig_f(gr[64 + u]);
            float g_ = tanh_f(gr[128 + u]);
            float o_ = sig_f(gr[192 + u]);
            c1 = f_ * c1 + i_ * g_;
            h1s[nxt + rr * HID + u] = o_ * tanh_f(c1);
        }

        x0 = p0; x1 = p1; x2 = p2; x3 = p3;
    }
    __syncthreads();

    // ---- Final FC + sigmoid on h1(511) (nxt of t=511 -> buffer 0)
    if (tid < 8) {
        int r = tid >> 1, o = tid & 1;
        float a = __ldg(&bfc[o]);
        for (int k = 0; k < HID; ++k)
            a = fmaf(h1s[0 + r * HID + k], __ldg(&Wfc[o * HID + k]), a);
        out[(row0 + r) * 2 + o] = sig_f(a);
    }
}

// ======================================================================
extern "C" void kernel_launch(void* const* d_in, const int* in_sizes, int n_in,
                              void* d_out, int out_size) {
    const int*   seq32 = (const int*)d_in[0];
    const float* emb   = (const float*)d_in[1];
    const float* Wih0  = (const float*)d_in[2];
    const float* Whh0  = (const float*)d_in[3];
    const float* bih0  = (const float*)d_in[4];
    const float* bhh0  = (const float*)d_in[5];
    const float* Wih1  = (const float*)d_in[6];
    const float* Whh1  = (const float*)d_in[7];
    const float* bih1  = (const float*)d_in[8];
    const float* bhh1  = (const float*)d_in[9];
    const float* Wfc   = (const float*)d_in[10];
    const float* bfc   = (const float*)d_in[11];
    float* out = (float*)d_out;

    float* tab = nullptr;
    cudaGetSymbolAddress((void**)&tab, g_tab);

    // dynamic smem for k_scan: wh1(256*68) + h0(512) + h1(512) + gA(1024)
    //                          + gB(1024) + tok4(512*4 ints)
    const int smem2 = (256 * WS + 512 + 512 + 1024 + 1024 + SEQ * 4) * 4;
    cudaFuncSetAttribute(k_scan, cudaFuncAttributeMaxDynamicSharedMemorySize, smem2);

    dim3 gtab((VOCAB + 127) / 128, 2);
    k_table<<<gtab, 256>>>(emb, Wih0, bih0, bhh0, tab);
    k_scan<<<BATCH / 4, 256, smem2>>>(seq32, tab, Whh0, Wih1, Whh1,
                                      bih1, bhh1, Wfc, bfc, out);
}